// round 1
// baseline (speedup 1.0000x reference)
#include <cuda_runtime.h>
#include <cuda_bf16.h>
#include <math.h>

// Problem sizes (fixed by the reference)
#define NN   8192
#define FIN  512
#define HID  256
#define OUT  64

// Scratch buffers (device globals; no allocations allowed)
__device__ float g_T1[NN * HID];   // x @ w1
__device__ float g_U1[NN * HID];   // winv @ T1
__device__ float g_H [NN * HID];   // relu(wav @ (f1*U1))
__device__ float g_T2[NN * OUT];   // H @ w2
__device__ float g_U2[NN * OUT];   // winv @ T2

// ---------------------------------------------------------------------------
// Tiled fp32 GEMM: C[M,N] = A[M,K] @ (optional rowscale s[k] *) B[K,N]
// Optional ReLU epilogue. All dims assumed divisible by tile sizes.
// ---------------------------------------------------------------------------
template <int BM, int BN, int BK, int TM, int TN, bool RELU, bool SCALE>
__global__ __launch_bounds__((BM / TM) * (BN / TN))
void sgemm_kernel(const float* __restrict__ A,
                  const float* __restrict__ B,
                  float* __restrict__ C,
                  const float* __restrict__ svec,
                  int M, int N, int K)
{
    constexpr int THREADS = (BM / TM) * (BN / TN);
    constexpr int AV = BK / 4;          // float4 per A-row chunk
    constexpr int BV = BN / 4;          // float4 per B-row chunk
    constexpr int LA = (BM * BK / 4) / THREADS;
    constexpr int LB = (BK * BN / 4) / THREADS;

    __shared__ float As[BK][BM + 4];
    __shared__ float Bs[BK][BN];

    const int tid = threadIdx.x;
    const int tx  = tid % (BN / TN);
    const int ty  = tid / (BN / TN);
    const int bm0 = blockIdx.y * BM;
    const int bn0 = blockIdx.x * BN;

    float4 aFrag[LA];
    float4 bFrag[LB];
    float  sFrag[LB];

    float acc[TM][TN];
#pragma unroll
    for (int i = 0; i < TM; i++)
#pragma unroll
        for (int j = 0; j < TN; j++) acc[i][j] = 0.0f;

    auto loadTiles = [&](int k0) {
#pragma unroll
        for (int i = 0; i < LA; i++) {
            int li = tid + THREADS * i;
            int m  = li / AV;
            int c  = li % AV;
            aFrag[i] = *reinterpret_cast<const float4*>(
                A + (size_t)(bm0 + m) * K + k0 + 4 * c);
        }
#pragma unroll
        for (int i = 0; i < LB; i++) {
            int li = tid + THREADS * i;
            int kk = li / BV;
            int c  = li % BV;
            bFrag[i] = *reinterpret_cast<const float4*>(
                B + (size_t)(k0 + kk) * N + bn0 + 4 * c);
            if (SCALE) sFrag[i] = svec[k0 + kk];
        }
    };

    auto storeTiles = [&]() {
#pragma unroll
        for (int i = 0; i < LA; i++) {
            int li = tid + THREADS * i;
            int m  = li / AV;
            int c  = li % AV;
            As[4 * c + 0][m] = aFrag[i].x;
            As[4 * c + 1][m] = aFrag[i].y;
            As[4 * c + 2][m] = aFrag[i].z;
            As[4 * c + 3][m] = aFrag[i].w;
        }
#pragma unroll
        for (int i = 0; i < LB; i++) {
            int li = tid + THREADS * i;
            int kk = li / BV;
            int c  = li % BV;
            float4 v = bFrag[i];
            if (SCALE) {
                v.x *= sFrag[i]; v.y *= sFrag[i];
                v.z *= sFrag[i]; v.w *= sFrag[i];
            }
            *reinterpret_cast<float4*>(&Bs[kk][4 * c]) = v;
        }
    };

    loadTiles(0);
    const int ntiles = K / BK;
    for (int kt = 0; kt < ntiles; kt++) {
        storeTiles();
        __syncthreads();
        if (kt + 1 < ntiles) loadTiles((kt + 1) * BK);

#pragma unroll
        for (int kk = 0; kk < BK; kk++) {
            float a[TM], b[TN];
#pragma unroll
            for (int i = 0; i < TM; i++) a[i] = As[kk][ty * TM + i];
#pragma unroll
            for (int j = 0; j < TN; j++) b[j] = Bs[kk][tx * TN + j];
#pragma unroll
            for (int i = 0; i < TM; i++)
#pragma unroll
                for (int j = 0; j < TN; j++)
                    acc[i][j] = fmaf(a[i], b[j], acc[i][j]);
        }
        __syncthreads();
    }

    // Epilogue (TN == 4 -> float4 stores)
#pragma unroll
    for (int i = 0; i < TM; i++) {
        float4 v;
        v.x = acc[i][0]; v.y = acc[i][1]; v.z = acc[i][2]; v.w = acc[i][3];
        if (RELU) {
            v.x = fmaxf(v.x, 0.0f); v.y = fmaxf(v.y, 0.0f);
            v.z = fmaxf(v.z, 0.0f); v.w = fmaxf(v.w, 0.0f);
        }
        *reinterpret_cast<float4*>(
            C + (size_t)(bm0 + ty * TM + i) * N + bn0 + tx * TN) = v;
    }
}

// ---------------------------------------------------------------------------
// In-place log_softmax over 64 columns, one warp per row.
// blockDim = (32, 8): 8 rows per block.
// ---------------------------------------------------------------------------
__global__ void log_softmax64_kernel(float* __restrict__ data)
{
    const int row  = blockIdx.x * 8 + threadIdx.y;
    const int lane = threadIdx.x;
    float* r = data + (size_t)row * OUT;

    float v0 = r[lane];
    float v1 = r[lane + 32];

    float m = fmaxf(v0, v1);
#pragma unroll
    for (int off = 16; off > 0; off >>= 1)
        m = fmaxf(m, __shfl_xor_sync(0xffffffffu, m, off));

    float e = expf(v0 - m) + expf(v1 - m);
#pragma unroll
    for (int off = 16; off > 0; off >>= 1)
        e += __shfl_xor_sync(0xffffffffu, e, off);

    const float lse = m + logf(e);
    r[lane]      = v0 - lse;
    r[lane + 32] = v1 - lse;
}

// ---------------------------------------------------------------------------
// kernel_launch
// inputs: x[8192,512], wavelets[8192,8192], wavelets_inv[8192,8192],
//         w1[512,256], f1[8192], w2[256,64], f2[8192]
// output: log_softmax(o) [8192,64] fp32
// ---------------------------------------------------------------------------
extern "C" void kernel_launch(void* const* d_in, const int* in_sizes, int n_in,
                              void* d_out, int out_size)
{
    const float* x    = (const float*)d_in[0];
    const float* wav  = (const float*)d_in[1];
    const float* winv = (const float*)d_in[2];
    const float* w1   = (const float*)d_in[3];
    const float* f1   = (const float*)d_in[4];
    const float* w2   = (const float*)d_in[5];
    const float* f2   = (const float*)d_in[6];
    float* out = (float*)d_out;

    float *T1, *U1, *H, *T2, *U2;
    cudaGetSymbolAddress((void**)&T1, g_T1);
    cudaGetSymbolAddress((void**)&U1, g_U1);
    cudaGetSymbolAddress((void**)&H,  g_H);
    cudaGetSymbolAddress((void**)&T2, g_T2);
    cudaGetSymbolAddress((void**)&U2, g_U2);

    // Layer 1
    // T1 = x @ w1                         [8192,512] @ [512,256]
    sgemm_kernel<128, 64, 16, 8, 4, false, false>
        <<<dim3(HID / 64, NN / 128), 256>>>(x, w1, T1, nullptr, NN, HID, FIN);
    // U1 = winv @ T1                      [8192,8192] @ [8192,256]
    sgemm_kernel<128, 64, 16, 8, 4, false, false>
        <<<dim3(HID / 64, NN / 128), 256>>>(winv, T1, U1, nullptr, NN, HID, NN);
    // H = relu(wav @ (f1 * U1))
    sgemm_kernel<128, 64, 16, 8, 4, true, true>
        <<<dim3(HID / 64, NN / 128), 256>>>(wav, U1, H, f1, NN, HID, NN);

    // Layer 2
    // T2 = H @ w2                         [8192,256] @ [256,64]
    sgemm_kernel<64, 64, 16, 4, 4, false, false>
        <<<dim3(OUT / 64, NN / 64), 256>>>(H, w2, T2, nullptr, NN, OUT, HID);
    // U2 = winv @ T2
    sgemm_kernel<64, 64, 16, 4, 4, false, false>
        <<<dim3(OUT / 64, NN / 64), 256>>>(winv, T2, U2, nullptr, NN, OUT, NN);
    // out = wav @ (f2 * U2)
    sgemm_kernel<64, 64, 16, 4, 4, false, true>
        <<<dim3(OUT / 64, NN / 64), 256>>>(wav, U2, out, f2, NN, OUT, NN);

    // log_softmax in place over the 64 columns
    log_softmax64_kernel<<<NN / 8, dim3(32, 8)>>>(out);
}

// round 3
// speedup vs baseline: 2.7475x; 2.7475x over previous
#include <cuda_runtime.h>
#include <cuda_bf16.h>
#include <cstdint>
#include <math.h>

// Problem sizes (fixed by the reference)
#define NN   8192
#define FIN  512
#define HID  256
#define OUTD 64

// ---------------------------------------------------------------------------
// Device scratch (bf16 hi/lo split operands). No allocations allowed.
// All "B" operands are stored K-major: B^T row-major, i.e. [n][k].
// ---------------------------------------------------------------------------
__device__ __nv_bfloat16 g_Whi[(size_t)NN * NN];     // wavelets hi      [m][k]
__device__ __nv_bfloat16 g_Wlo[(size_t)NN * NN];     // wavelets lo
__device__ __nv_bfloat16 g_Vhi[(size_t)NN * NN];     // wavelets_inv hi  [m][k]
__device__ __nv_bfloat16 g_Vlo[(size_t)NN * NN];     // wavelets_inv lo
__device__ __nv_bfloat16 g_Xhi[(size_t)NN * FIN];    // x                [m][k]
__device__ __nv_bfloat16 g_Xlo[(size_t)NN * FIN];
__device__ __nv_bfloat16 g_W1thi[(size_t)HID * FIN]; // w1^T  [256][512]
__device__ __nv_bfloat16 g_W1tlo[(size_t)HID * FIN];
__device__ __nv_bfloat16 g_T1thi[(size_t)HID * NN];  // T1^T  [256][8192]
__device__ __nv_bfloat16 g_T1tlo[(size_t)HID * NN];
__device__ __nv_bfloat16 g_U1thi[(size_t)HID * NN];  // (f1*U1)^T [256][8192]
__device__ __nv_bfloat16 g_U1tlo[(size_t)HID * NN];
__device__ __nv_bfloat16 g_Hhi[(size_t)NN * HID];    // H row-major [8192][256]
__device__ __nv_bfloat16 g_Hlo[(size_t)NN * HID];
__device__ __nv_bfloat16 g_W2thi[(size_t)OUTD * HID];// w2^T  [64][256]
__device__ __nv_bfloat16 g_W2tlo[(size_t)OUTD * HID];
__device__ __nv_bfloat16 g_T2thi[(size_t)OUTD * NN]; // T2^T  [64][8192]
__device__ __nv_bfloat16 g_T2tlo[(size_t)OUTD * NN];
__device__ __nv_bfloat16 g_U2thi[(size_t)OUTD * NN]; // (f2*U2)^T [64][8192]
__device__ __nv_bfloat16 g_U2tlo[(size_t)OUTD * NN];

// ---------------------------------------------------------------------------
// Baseline-PTX helpers (sm_80+ features only: cp.async, ldmatrix, mma.sync)
// ---------------------------------------------------------------------------
__device__ __forceinline__ uint32_t smem_u32(const void* p) {
    uint32_t a;
    asm("{ .reg .u64 t; cvta.to.shared.u64 t, %1; cvt.u32.u64 %0, t; }"
        : "=r"(a) : "l"(p));
    return a;
}

__device__ __forceinline__ void cp_async16(uint32_t s, const void* g) {
    asm volatile("cp.async.cg.shared.global [%0], [%1], 16;"
                 :: "r"(s), "l"(g) : "memory");
}

__device__ __forceinline__ void ldmat4(uint32_t* r, uint32_t a) {
    asm volatile("ldmatrix.sync.aligned.m8n8.x4.shared.b16 {%0,%1,%2,%3}, [%4];"
                 : "=r"(r[0]), "=r"(r[1]), "=r"(r[2]), "=r"(r[3]) : "r"(a));
}

__device__ __forceinline__ void mma_bf16(float* c, const uint32_t* a,
                                         const uint32_t* b) {
    asm volatile(
        "mma.sync.aligned.m16n8k16.row.col.f32.bf16.bf16.f32 "
        "{%0,%1,%2,%3}, {%4,%5,%6,%7}, {%8,%9}, {%0,%1,%2,%3};"
        : "+f"(c[0]), "+f"(c[1]), "+f"(c[2]), "+f"(c[3])
        : "r"(a[0]), "r"(a[1]), "r"(a[2]), "r"(a[3]), "r"(b[0]), "r"(b[1]));
}

// ---------------------------------------------------------------------------
// Split-precision bf16 warp-MMA GEMM:
//   C[8192, Ncols] = A[8192, K] @ B[Ncols, K]^T
// A,B each given as bf16 (hi, lo); per k16: hi*hi + hi*lo + lo*hi.
// SMEM tiles: rows of 128B (64 bf16 = BK), XOR-swizzled, 3-stage cp.async.
// EPI: 0 = transposed bf16 hi/lo  out[n*8192 + m]
//      1 = row-major  bf16 hi/lo  out[m*HID + n]
//      2 = fp32 row-major         outF[m*OUTD + n]
// ---------------------------------------------------------------------------
template <int BM, int BN, int WM, int WN, int NTHR, int EPI, bool RELU, bool SCALE>
__global__ void __launch_bounds__(NTHR, 1)
gemm_mma_kernel(const __nv_bfloat16* __restrict__ Ahi,
                const __nv_bfloat16* __restrict__ Alo,
                const __nv_bfloat16* __restrict__ Bhi,
                const __nv_bfloat16* __restrict__ Blo,
                int K,
                float* __restrict__ outF,
                __nv_bfloat16* __restrict__ oHi,
                __nv_bfloat16* __restrict__ oLo,
                const float* __restrict__ svec)
{
    constexpr int WCOLS = BN / WN;         // warps along N
    constexpr int MT  = WM / 16;           // 16-row m tiles per warp
    constexpr int NTT = WN / 16;           // 16-col n tiles per warp (x4 ldmatrix)
    constexpr int NT8 = WN / 8;            // 8-col n tiles per warp (mma)
    constexpr int A_B = BM * 128;          // bytes per A tile (one operand)
    constexpr int B_B = BN * 128;
    constexpr int STAGE = 2 * A_B + 2 * B_B;

    extern __shared__ __align__(128) char smem[];
    const uint32_t sbase = smem_u32(smem);

    const int tid  = threadIdx.x;
    const int w    = tid >> 5;
    const int lane = tid & 31;
    const int wm = (w / WCOLS) * WM;
    const int wn = (w % WCOLS) * WN;
    const int m0 = blockIdx.y * BM;
    const int n0 = blockIdx.x * BN;
    const int T  = K >> 6;                 // K tiles of 64

    float acc[MT][NT8][4];
#pragma unroll
    for (int i = 0; i < MT; i++)
#pragma unroll
        for (int j = 0; j < NT8; j++)
#pragma unroll
            for (int q = 0; q < 4; q++) acc[i][j][q] = 0.0f;

    auto load_stage = [&](int s, int kt) {
        const uint32_t st = sbase + s * STAGE;
        const int kel = kt * 64;
#pragma unroll
        for (int id = tid; id < BM * 8; id += NTHR) {
            const int r = id >> 3, c = id & 7;
            const uint32_t dst = st + r * 128 + ((c ^ (r & 7)) << 4);
            const size_t go = (size_t)(m0 + r) * K + kel + c * 8;
            cp_async16(dst,       Ahi + go);
            cp_async16(dst + A_B, Alo + go);
        }
#pragma unroll
        for (int id = tid; id < BN * 8; id += NTHR) {
            const int r = id >> 3, c = id & 7;
            const uint32_t dst = st + 2 * A_B + r * 128 + ((c ^ (r & 7)) << 4);
            const size_t go = (size_t)(n0 + r) * K + kel + c * 8;
            cp_async16(dst,       Bhi + go);
            cp_async16(dst + B_B, Blo + go);
        }
        asm volatile("cp.async.commit_group;" ::: "memory");
    };

    auto compute_stage = [&](int s) {
        const uint32_t aBase = sbase + s * STAGE;
        const uint32_t bBase = aBase + 2 * A_B;
#pragma unroll
        for (int k16 = 0; k16 < 4; k16++) {
            uint32_t ah[MT][4], al[MT][4];
#pragma unroll
            for (int mt = 0; mt < MT; mt++) {
                const int r = wm + mt * 16 + (lane & 15);
                const int c = k16 * 2 + (lane >> 4);
                const uint32_t ad = aBase + r * 128 + ((c ^ (r & 7)) << 4);
                ldmat4(ah[mt], ad);
                ldmat4(al[mt], ad + A_B);
            }
            uint32_t bh[NTT][4], bl[NTT][4];
#pragma unroll
            for (int nt = 0; nt < NTT; nt++) {
                const int r = wn + nt * 16 + ((lane >> 4) << 3) + (lane & 7);
                const int c = k16 * 2 + ((lane >> 3) & 1);
                const uint32_t bd = bBase + r * 128 + ((c ^ (r & 7)) << 4);
                ldmat4(bh[nt], bd);
                ldmat4(bl[nt], bd + B_B);
            }
#pragma unroll
            for (int mt = 0; mt < MT; mt++)
#pragma unroll
                for (int n8 = 0; n8 < NT8; n8++) {
                    const uint32_t* bhp = &bh[n8 >> 1][(n8 & 1) * 2];
                    const uint32_t* blp = &bl[n8 >> 1][(n8 & 1) * 2];
                    mma_bf16(acc[mt][n8], ah[mt], bhp);
                    mma_bf16(acc[mt][n8], ah[mt], blp);
                    mma_bf16(acc[mt][n8], al[mt], bhp);
                }
        }
    };

    // 3-stage pipeline
    load_stage(0, 0);
    if (T > 1) load_stage(1, 1);
    for (int kt = 0; kt < T; kt++) {
        if (kt + 2 < T) load_stage((kt + 2) % 3, kt + 2);
        const int rem = T - 1 - kt;
        if (rem >= 2)      asm volatile("cp.async.wait_group 2;" ::: "memory");
        else if (rem == 1) asm volatile("cp.async.wait_group 1;" ::: "memory");
        else               asm volatile("cp.async.wait_group 0;" ::: "memory");
        __syncthreads();
        compute_stage(kt % 3);
        __syncthreads();
    }

    // Epilogue
#pragma unroll
    for (int mt = 0; mt < MT; mt++) {
        const int mb = m0 + wm + mt * 16 + (lane >> 2);
        const float s0 = SCALE ? svec[mb]     : 1.0f;
        const float s1 = SCALE ? svec[mb + 8] : 1.0f;
#pragma unroll
        for (int n8 = 0; n8 < NT8; n8++) {
            const int nb = n0 + wn + n8 * 8 + 2 * (lane & 3);
#pragma unroll
            for (int i = 0; i < 2; i++) {
                float v0 = acc[mt][n8][i]     * s0;   // row mb,   col nb+i
                float v1 = acc[mt][n8][2 + i] * s1;   // row mb+8, col nb+i
                if (RELU) { v0 = fmaxf(v0, 0.0f); v1 = fmaxf(v1, 0.0f); }
                const int n = nb + i;
                if (EPI == 2) {
                    outF[(size_t)mb * OUTD + n]       = v0;
                    outF[(size_t)(mb + 8) * OUTD + n] = v1;
                } else {
                    const __nv_bfloat16 h0 = __float2bfloat16(v0);
                    const __nv_bfloat16 l0 = __float2bfloat16(v0 - __bfloat162float(h0));
                    const __nv_bfloat16 h1 = __float2bfloat16(v1);
                    const __nv_bfloat16 l1 = __float2bfloat16(v1 - __bfloat162float(h1));
                    size_t o0, o1;
                    if (EPI == 0) {
                        o0 = (size_t)n * NN + mb;
                        o1 = (size_t)n * NN + mb + 8;
                    } else {
                        o0 = (size_t)mb * HID + n;
                        o1 = (size_t)(mb + 8) * HID + n;
                    }
                    oHi[o0] = h0; oLo[o0] = l0;
                    oHi[o1] = h1; oLo[o1] = l1;
                }
            }
        }
    }
}

// ---------------------------------------------------------------------------
// fp32 -> bf16 hi/lo split (elementwise, float4 vectorized)
// ---------------------------------------------------------------------------
__global__ void split4_kernel(const float4* __restrict__ in,
                              __nv_bfloat16* __restrict__ hi,
                              __nv_bfloat16* __restrict__ lo,
                              size_t n4)
{
    const size_t stride = (size_t)gridDim.x * blockDim.x;
    __nv_bfloat162* H = reinterpret_cast<__nv_bfloat162*>(hi);
    __nv_bfloat162* L = reinterpret_cast<__nv_bfloat162*>(lo);
    for (size_t i = blockIdx.x * (size_t)blockDim.x + threadIdx.x; i < n4; i += stride) {
        float4 v = in[i];
        __nv_bfloat16 h0 = __float2bfloat16(v.x);
        __nv_bfloat16 h1 = __float2bfloat16(v.y);
        __nv_bfloat16 h2 = __float2bfloat16(v.z);
        __nv_bfloat16 h3 = __float2bfloat16(v.w);
        __nv_bfloat16 l0 = __float2bfloat16(v.x - __bfloat162float(h0));
        __nv_bfloat16 l1 = __float2bfloat16(v.y - __bfloat162float(h1));
        __nv_bfloat16 l2 = __float2bfloat16(v.z - __bfloat162float(h2));
        __nv_bfloat16 l3 = __float2bfloat16(v.w - __bfloat162float(h3));
        H[2 * i]     = __halves2bfloat162(h0, h1);
        H[2 * i + 1] = __halves2bfloat162(h2, h3);
        L[2 * i]     = __halves2bfloat162(l0, l1);
        L[2 * i + 1] = __halves2bfloat162(l2, l3);
    }
}

// fp32 [R,C] row-major -> transposed bf16 hi/lo [C,R] (small weights)
__global__ void split_t_kernel(const float* __restrict__ in,
                               __nv_bfloat16* __restrict__ hiT,
                               __nv_bfloat16* __restrict__ loT,
                               int R, int C)
{
    const int idx = blockIdx.x * blockDim.x + threadIdx.x;
    if (idx < R * C) {
        const int r = idx / C, c = idx % C;
        const float v = in[idx];
        const __nv_bfloat16 h = __float2bfloat16(v);
        const __nv_bfloat16 l = __float2bfloat16(v - __bfloat162float(h));
        hiT[(size_t)c * R + r] = h;
        loT[(size_t)c * R + r] = l;
    }
}

// In-place log_softmax over 64 cols, one warp per row, 8 rows/block
__global__ void log_softmax64_kernel(float* __restrict__ data)
{
    const int row  = blockIdx.x * 8 + threadIdx.y;
    const int lane = threadIdx.x;
    float* r = data + (size_t)row * OUTD;

    float v0 = r[lane];
    float v1 = r[lane + 32];

    float m = fmaxf(v0, v1);
#pragma unroll
    for (int off = 16; off > 0; off >>= 1)
        m = fmaxf(m, __shfl_xor_sync(0xffffffffu, m, off));

    float e = expf(v0 - m) + expf(v1 - m);
#pragma unroll
    for (int off = 16; off > 0; off >>= 1)
        e += __shfl_xor_sync(0xffffffffu, e, off);

    const float lse = m + logf(e);
    r[lane]      = v0 - lse;
    r[lane + 32] = v1 - lse;
}

// ---------------------------------------------------------------------------
// Host side
// ---------------------------------------------------------------------------
extern "C" void kernel_launch(void* const* d_in, const int* in_sizes, int n_in,
                              void* d_out, int out_size)
{
    const float* x    = (const float*)d_in[0];
    const float* wav  = (const float*)d_in[1];
    const float* winv = (const float*)d_in[2];
    const float* w1   = (const float*)d_in[3];
    const float* f1   = (const float*)d_in[4];
    const float* w2   = (const float*)d_in[5];
    const float* f2   = (const float*)d_in[6];
    float* out = (float*)d_out;

    __nv_bfloat16 *Whi, *Wlo, *Vhi, *Vlo, *Xhi, *Xlo, *W1thi, *W1tlo;
    __nv_bfloat16 *T1thi, *T1tlo, *U1thi, *U1tlo, *Hhi, *Hlo;
    __nv_bfloat16 *W2thi, *W2tlo, *T2thi, *T2tlo, *U2thi, *U2tlo;
    cudaGetSymbolAddress((void**)&Whi, g_Whi);     cudaGetSymbolAddress((void**)&Wlo, g_Wlo);
    cudaGetSymbolAddress((void**)&Vhi, g_Vhi);     cudaGetSymbolAddress((void**)&Vlo, g_Vlo);
    cudaGetSymbolAddress((void**)&Xhi, g_Xhi);     cudaGetSymbolAddress((void**)&Xlo, g_Xlo);
    cudaGetSymbolAddress((void**)&W1thi, g_W1thi); cudaGetSymbolAddress((void**)&W1tlo, g_W1tlo);
    cudaGetSymbolAddress((void**)&T1thi, g_T1thi); cudaGetSymbolAddress((void**)&T1tlo, g_T1tlo);
    cudaGetSymbolAddress((void**)&U1thi, g_U1thi); cudaGetSymbolAddress((void**)&U1tlo, g_U1tlo);
    cudaGetSymbolAddress((void**)&Hhi, g_Hhi);     cudaGetSymbolAddress((void**)&Hlo, g_Hlo);
    cudaGetSymbolAddress((void**)&W2thi, g_W2thi); cudaGetSymbolAddress((void**)&W2tlo, g_W2tlo);
    cudaGetSymbolAddress((void**)&T2thi, g_T2thi); cudaGetSymbolAddress((void**)&T2tlo, g_T2tlo);
    cudaGetSymbolAddress((void**)&U2thi, g_U2thi); cudaGetSymbolAddress((void**)&U2tlo, g_U2tlo);

    // --- Split conversions ---
    split4_kernel<<<2048, 256>>>((const float4*)wav,  Whi, Wlo, (size_t)NN * NN / 4);
    split4_kernel<<<2048, 256>>>((const float4*)winv, Vhi, Vlo, (size_t)NN * NN / 4);
    split4_kernel<<<1024, 256>>>((const float4*)x,    Xhi, Xlo, (size_t)NN * FIN / 4);
    split_t_kernel<<<(FIN * HID + 255) / 256, 256>>>(w1, W1thi, W1tlo, FIN, HID);
    split_t_kernel<<<(HID * OUTD + 255) / 256, 256>>>(w2, W2thi, W2tlo, HID, OUTD);

    // --- SMEM attributes ---
    constexpr int SMEM_BIG   = 3 * (4 * 128 * 128);  // 196608
    constexpr int SMEM_SMALL = 3 * (4 * 64 * 128);   // 98304

    cudaFuncSetAttribute((const void*)gemm_mma_kernel<128,128,64,32,256,0,false,false>,
                         cudaFuncAttributeMaxDynamicSharedMemorySize, SMEM_BIG);
    cudaFuncSetAttribute((const void*)gemm_mma_kernel<128,128,64,32,256,0,false,true>,
                         cudaFuncAttributeMaxDynamicSharedMemorySize, SMEM_BIG);
    cudaFuncSetAttribute((const void*)gemm_mma_kernel<128,128,64,32,256,1,true,false>,
                         cudaFuncAttributeMaxDynamicSharedMemorySize, SMEM_BIG);
    cudaFuncSetAttribute((const void*)gemm_mma_kernel<64,64,32,32,128,0,false,false>,
                         cudaFuncAttributeMaxDynamicSharedMemorySize, SMEM_SMALL);
    cudaFuncSetAttribute((const void*)gemm_mma_kernel<64,64,32,32,128,0,false,true>,
                         cudaFuncAttributeMaxDynamicSharedMemorySize, SMEM_SMALL);
    cudaFuncSetAttribute((const void*)gemm_mma_kernel<64,64,32,32,128,2,false,false>,
                         cudaFuncAttributeMaxDynamicSharedMemorySize, SMEM_SMALL);

    // --- GEMM chain ---
    // T1^T = (x @ w1)^T                      A=x [8192,512], B=w1^T [256,512]
    gemm_mma_kernel<128,128,64,32,256,0,false,false>
        <<<dim3(HID/128, NN/128), 256, SMEM_BIG>>>(
            Xhi, Xlo, W1thi, W1tlo, FIN, nullptr, T1thi, T1tlo, nullptr);
    // (f1*U1)^T = (f1 * (winv @ T1))^T       A=winv, B=T1^T [256,8192]
    gemm_mma_kernel<128,128,64,32,256,0,false,true>
        <<<dim3(HID/128, NN/128), 256, SMEM_BIG>>>(
            Vhi, Vlo, T1thi, T1tlo, NN, nullptr, U1thi, U1tlo, f1);
    // H = relu(wav @ (f1*U1))   row-major [8192,256]
    gemm_mma_kernel<128,128,64,32,256,1,true,false>
        <<<dim3(HID/128, NN/128), 256, SMEM_BIG>>>(
            Whi, Wlo, U1thi, U1tlo, NN, nullptr, Hhi, Hlo, nullptr);
    // T2^T = (H @ w2)^T                      A=H [8192,256], B=w2^T [64,256]
    gemm_mma_kernel<64,64,32,32,128,0,false,false>
        <<<dim3(OUTD/64, NN/64), 128, SMEM_SMALL>>>(
            Hhi, Hlo, W2thi, W2tlo, HID, nullptr, T2thi, T2tlo, nullptr);
    // (f2*U2)^T = (f2 * (winv @ T2))^T       A=winv, B=T2^T [64,8192]
    gemm_mma_kernel<64,64,32,32,128,0,false,true>
        <<<dim3(OUTD/64, NN/64), 128, SMEM_SMALL>>>(
            Vhi, Vlo, T2thi, T2tlo, NN, nullptr, U2thi, U2tlo, f2);
    // out = wav @ (f2*U2)   fp32 [8192,64]
    gemm_mma_kernel<64,64,32,32,128,2,false,false>
        <<<dim3(OUTD/64, NN/64), 128, SMEM_SMALL>>>(
            Whi, Wlo, U2thi, U2tlo, NN, out, nullptr, nullptr, nullptr);

    // log_softmax in place
    log_softmax64_kernel<<<NN / 8, dim3(32, 8)>>>(out);
}

// round 4
// speedup vs baseline: 3.1170x; 1.1345x over previous
#include <cuda_runtime.h>
#include <cuda_bf16.h>
#include <cstdint>
#include <math.h>

// Problem sizes (fixed by the reference)
#define NN   8192
#define FIN  512
#define HID  256
#define OUTD 64

// ---------------------------------------------------------------------------
// Device scratch (bf16 hi/lo intermediates only; wavelets stay fp32 in-place).
// All "B" operands are stored K-major: B^T row-major, i.e. [n][k].
// ---------------------------------------------------------------------------
__device__ __nv_bfloat16 g_W1thi[(size_t)HID * FIN]; // w1^T  [256][512]
__device__ __nv_bfloat16 g_W1tlo[(size_t)HID * FIN];
__device__ __nv_bfloat16 g_T1thi[(size_t)HID * NN];  // T1^T  [256][8192]
__device__ __nv_bfloat16 g_T1tlo[(size_t)HID * NN];
__device__ __nv_bfloat16 g_U1thi[(size_t)HID * NN];  // (f1*U1)^T [256][8192]
__device__ __nv_bfloat16 g_U1tlo[(size_t)HID * NN];
__device__ __nv_bfloat16 g_Hhi[(size_t)NN * HID];    // H row-major [8192][256]
__device__ __nv_bfloat16 g_Hlo[(size_t)NN * HID];
__device__ __nv_bfloat16 g_W2thi[(size_t)OUTD * HID];// w2^T  [64][256]
__device__ __nv_bfloat16 g_W2tlo[(size_t)OUTD * HID];
__device__ __nv_bfloat16 g_T2thi[(size_t)OUTD * NN]; // T2^T  [64][8192]
__device__ __nv_bfloat16 g_T2tlo[(size_t)OUTD * NN];
__device__ __nv_bfloat16 g_U2thi[(size_t)OUTD * NN]; // (f2*U2)^T [64][8192]
__device__ __nv_bfloat16 g_U2tlo[(size_t)OUTD * NN];

// ---------------------------------------------------------------------------
// Baseline-PTX helpers (sm_80+ features only: cp.async, ldmatrix, mma.sync)
// ---------------------------------------------------------------------------
__device__ __forceinline__ uint32_t smem_u32(const void* p) {
    uint32_t a;
    asm("{ .reg .u64 t; cvta.to.shared.u64 t, %1; cvt.u32.u64 %0, t; }"
        : "=r"(a) : "l"(p));
    return a;
}

__device__ __forceinline__ void cp_async16(uint32_t s, const void* g) {
    asm volatile("cp.async.cg.shared.global [%0], [%1], 16;"
                 :: "r"(s), "l"(g) : "memory");
}

__device__ __forceinline__ void ldmat4(uint32_t* r, uint32_t a) {
    asm volatile("ldmatrix.sync.aligned.m8n8.x4.shared.b16 {%0,%1,%2,%3}, [%4];"
                 : "=r"(r[0]), "=r"(r[1]), "=r"(r[2]), "=r"(r[3]) : "r"(a));
}

__device__ __forceinline__ void mma_bf16(float* c, const uint32_t* a,
                                         const uint32_t* b) {
    asm volatile(
        "mma.sync.aligned.m16n8k16.row.col.f32.bf16.bf16.f32 "
        "{%0,%1,%2,%3}, {%4,%5,%6,%7}, {%8,%9}, {%0,%1,%2,%3};"
        : "+f"(c[0]), "+f"(c[1]), "+f"(c[2]), "+f"(c[3])
        : "r"(a[0]), "r"(a[1]), "r"(a[2]), "r"(a[3]), "r"(b[0]), "r"(b[1]));
}

// Split a float2 into packed bf16x2 hi and packed bf16x2 lo (low half = .x).
__device__ __forceinline__ void split2(float fx, float fy,
                                       uint32_t& hp, uint32_t& lp) {
    asm("cvt.rn.bf16x2.f32 %0, %1, %2;" : "=r"(hp) : "f"(fy), "f"(fx));
    const float r0 = fx - __uint_as_float(hp << 16);
    const float r1 = fy - __uint_as_float(hp & 0xFFFF0000u);
    asm("cvt.rn.bf16x2.f32 %0, %1, %2;" : "=r"(lp) : "f"(r1), "f"(r0));
}

// fp32-A SMEM swizzle: 16B chunk permutation, conflict-free for the LDS.64
// fragment reads (rows r, r+4 in the same phase hit disjoint bank groups).
__device__ __forceinline__ int axmap(int r) {
    return ((r & 3) << 1) | ((r >> 2) & 1);
}

// ---------------------------------------------------------------------------
// Split-precision bf16 warp-MMA GEMM:
//   C[8192, Ncols] = A[8192, K] @ B[Ncols, K]^T
// Per k16: Ahi*Bhi + Ahi*Blo + Alo*Bhi into fp32 accumulators.
// APREC: 1 = A is fp32 (converted to hi/lo in registers after cp.async)
//        0 = A is bf16 hi/lo pair (ldmatrix path)
// B is always a bf16 hi/lo pair (our epilogues produce it).
// EPI: 0 = transposed bf16 hi/lo  out[n*8192 + m]
//      1 = row-major  bf16 hi/lo  out[m*HID + n]
//      2 = fp32 row-major         outF[m*OUTD + n]
// ---------------------------------------------------------------------------
template <int BM, int BN, int WM, int WN, int NTHR, int APREC, int EPI,
          bool RELU, bool SCALE>
__global__ void __launch_bounds__(NTHR, 1)
gemm_mma_kernel(const void* __restrict__ A0,   // fp32 (APREC=1) or bf16 hi
                const void* __restrict__ A1,   // unused       or bf16 lo
                const __nv_bfloat16* __restrict__ Bhi,
                const __nv_bfloat16* __restrict__ Blo,
                int K,
                float* __restrict__ outF,
                __nv_bfloat16* __restrict__ oHi,
                __nv_bfloat16* __restrict__ oLo,
                const float* __restrict__ svec)
{
    constexpr int WCOLS = BN / WN;         // warps along N
    constexpr int MT  = WM / 16;           // 16-row m tiles per warp
    constexpr int NTT = WN / 16;           // 16-col n tiles per warp
    constexpr int NT8 = WN / 8;            // 8-col n tiles per warp
    constexpr int A_BYTES = BM * 256;      // fp32 tile OR hi+lo bf16 tiles
    constexpr int A_HALF  = BM * 128;      // bf16 single-operand tile
    constexpr int B_B = BN * 128;
    constexpr int STAGE = A_BYTES + 2 * B_B;

    extern __shared__ __align__(128) char smem[];
    const uint32_t sbase = smem_u32(smem);

    const int tid  = threadIdx.x;
    const int w    = tid >> 5;
    const int lane = tid & 31;
    const int wm = (w / WCOLS) * WM;
    const int wn = (w % WCOLS) * WN;
    const int m0 = blockIdx.y * BM;
    const int n0 = blockIdx.x * BN;
    const int T  = K >> 6;                 // K tiles of 64

    float acc[MT][NT8][4];
#pragma unroll
    for (int i = 0; i < MT; i++)
#pragma unroll
        for (int j = 0; j < NT8; j++)
#pragma unroll
            for (int q = 0; q < 4; q++) acc[i][j][q] = 0.0f;

    auto load_stage = [&](int s, int kt) {
        const uint32_t st = sbase + s * STAGE;
        const int kel = kt * 64;
        if (APREC == 1) {
            const float* Af = (const float*)A0;
#pragma unroll
            for (int id = tid; id < BM * 16; id += NTHR) {
                const int r = id >> 4, c = id & 15;
                const uint32_t dst = st + r * 256 + ((c ^ axmap(r)) << 4);
                cp_async16(dst, Af + (size_t)(m0 + r) * K + kel + c * 4);
            }
        } else {
            const __nv_bfloat16* Ahi = (const __nv_bfloat16*)A0;
            const __nv_bfloat16* Alo = (const __nv_bfloat16*)A1;
#pragma unroll
            for (int id = tid; id < BM * 8; id += NTHR) {
                const int r = id >> 3, c = id & 7;
                const uint32_t dst = st + r * 128 + ((c ^ (r & 7)) << 4);
                const size_t go = (size_t)(m0 + r) * K + kel + c * 8;
                cp_async16(dst,          Ahi + go);
                cp_async16(dst + A_HALF, Alo + go);
            }
        }
#pragma unroll
        for (int id = tid; id < BN * 8; id += NTHR) {
            const int r = id >> 3, c = id & 7;
            const uint32_t dst = st + A_BYTES + r * 128 + ((c ^ (r & 7)) << 4);
            const size_t go = (size_t)(n0 + r) * K + kel + c * 8;
            cp_async16(dst,       Bhi + go);
            cp_async16(dst + B_B, Blo + go);
        }
        asm volatile("cp.async.commit_group;" ::: "memory");
    };

    auto compute_stage = [&](int s) {
        const uint32_t aBase = sbase + s * STAGE;
        const uint32_t bBase = aBase + A_BYTES;
#pragma unroll
        for (int k16 = 0; k16 < 4; k16++) {
            uint32_t ah[MT][4], al[MT][4];
            if (APREC == 1) {
#pragma unroll
                for (int mt = 0; mt < MT; mt++) {
                    const int rb = wm + mt * 16 + (lane >> 2);
                    const int kb = k16 * 16 + (lane & 3) * 2;
#pragma unroll
                    for (int h = 0; h < 2; h++) {      // k offset 0 / +8
#pragma unroll
                        for (int rr = 0; rr < 2; rr++) { // row offset 0 / +8
                            const int row = rb + 8 * rr;
                            const int k   = kb + 8 * h;
                            const int c   = k >> 2;
                            const uint32_t off = aBase + row * 256 +
                                ((c ^ axmap(row)) << 4) + (k & 3) * 4;
                            float2 f;
                            asm volatile("ld.shared.v2.f32 {%0,%1}, [%2];"
                                         : "=f"(f.x), "=f"(f.y) : "r"(off));
                            split2(f.x, f.y, ah[mt][h * 2 + rr], al[mt][h * 2 + rr]);
                        }
                    }
                }
            } else {
#pragma unroll
                for (int mt = 0; mt < MT; mt++) {
                    const int r = wm + mt * 16 + (lane & 15);
                    const int c = k16 * 2 + (lane >> 4);
                    const uint32_t ad = aBase + r * 128 + ((c ^ (r & 7)) << 4);
                    ldmat4(ah[mt], ad);
                    ldmat4(al[mt], ad + A_HALF);
                }
            }
            uint32_t bh[NTT][4], bl[NTT][4];
#pragma unroll
            for (int nt = 0; nt < NTT; nt++) {
                const int r = wn + nt * 16 + ((lane >> 4) << 3) + (lane & 7);
                const int c = k16 * 2 + ((lane >> 3) & 1);
                const uint32_t bd = bBase + r * 128 + ((c ^ (r & 7)) << 4);
                ldmat4(bh[nt], bd);
                ldmat4(bl[nt], bd + B_B);
            }
#pragma unroll
            for (int mt = 0; mt < MT; mt++)
#pragma unroll
                for (int n8 = 0; n8 < NT8; n8++) {
                    const uint32_t* bhp = &bh[n8 >> 1][(n8 & 1) * 2];
                    const uint32_t* blp = &bl[n8 >> 1][(n8 & 1) * 2];
                    mma_bf16(acc[mt][n8], ah[mt], bhp);
                    mma_bf16(acc[mt][n8], ah[mt], blp);
                    mma_bf16(acc[mt][n8], al[mt], bhp);
                }
        }
    };

    // 3-stage cp.async pipeline
    load_stage(0, 0);
    if (T > 1) load_stage(1, 1);
    for (int kt = 0; kt < T; kt++) {
        if (kt + 2 < T) load_stage((kt + 2) % 3, kt + 2);
        const int rem = T - 1 - kt;
        if (rem >= 2)      asm volatile("cp.async.wait_group 2;" ::: "memory");
        else if (rem == 1) asm volatile("cp.async.wait_group 1;" ::: "memory");
        else               asm volatile("cp.async.wait_group 0;" ::: "memory");
        __syncthreads();
        compute_stage(kt % 3);
        __syncthreads();
    }

    // Epilogue
#pragma unroll
    for (int mt = 0; mt < MT; mt++) {
        const int mb = m0 + wm + mt * 16 + (lane >> 2);
        const float s0 = SCALE ? svec[mb]     : 1.0f;
        const float s1 = SCALE ? svec[mb + 8] : 1.0f;
#pragma unroll
        for (int n8 = 0; n8 < NT8; n8++) {
            const int nb = n0 + wn + n8 * 8 + 2 * (lane & 3);
#pragma unroll
            for (int i = 0; i < 2; i++) {
                float v0 = acc[mt][n8][i]     * s0;   // row mb,   col nb+i
                float v1 = acc[mt][n8][2 + i] * s1;   // row mb+8, col nb+i
                if (RELU) { v0 = fmaxf(v0, 0.0f); v1 = fmaxf(v1, 0.0f); }
                const int n = nb + i;
                if (EPI == 2) {
                    outF[(size_t)mb * OUTD + n]       = v0;
                    outF[(size_t)(mb + 8) * OUTD + n] = v1;
                } else {
                    const __nv_bfloat16 h0 = __float2bfloat16(v0);
                    const __nv_bfloat16 l0 = __float2bfloat16(v0 - __bfloat162float(h0));
                    const __nv_bfloat16 h1 = __float2bfloat16(v1);
                    const __nv_bfloat16 l1 = __float2bfloat16(v1 - __bfloat162float(h1));
                    size_t o0, o1;
                    if (EPI == 0) {
                        o0 = (size_t)n * NN + mb;
                        o1 = (size_t)n * NN + mb + 8;
                    } else {
                        o0 = (size_t)mb * HID + n;
                        o1 = (size_t)(mb + 8) * HID + n;
                    }
                    oHi[o0] = h0; oLo[o0] = l0;
                    oHi[o1] = h1; oLo[o1] = l1;
                }
            }
        }
    }
}

// fp32 [R,C] row-major -> transposed bf16 hi/lo [C,R] (small weights)
__global__ void split_t_kernel(const float* __restrict__ in,
                               __nv_bfloat16* __restrict__ hiT,
                               __nv_bfloat16* __restrict__ loT,
                               int R, int C)
{
    const int idx = blockIdx.x * blockDim.x + threadIdx.x;
    if (idx < R * C) {
        const int r = idx / C, c = idx % C;
        const float v = in[idx];
        const __nv_bfloat16 h = __float2bfloat16(v);
        const __nv_bfloat16 l = __float2bfloat16(v - __bfloat162float(h));
        hiT[(size_t)c * R + r] = h;
        loT[(size_t)c * R + r] = l;
    }
}

// In-place log_softmax over 64 cols, one warp per row, 8 rows/block
__global__ void log_softmax64_kernel(float* __restrict__ data)
{
    const int row  = blockIdx.x * 8 + threadIdx.y;
    const int lane = threadIdx.x;
    float* r = data + (size_t)row * OUTD;

    float v0 = r[lane];
    float v1 = r[lane + 32];

    float m = fmaxf(v0, v1);
#pragma unroll
    for (int off = 16; off > 0; off >>= 1)
        m = fmaxf(m, __shfl_xor_sync(0xffffffffu, m, off));

    float e = expf(v0 - m) + expf(v1 - m);
#pragma unroll
    for (int off = 16; off > 0; off >>= 1)
        e += __shfl_xor_sync(0xffffffffu, e, off);

    const float lse = m + logf(e);
    r[lane]      = v0 - lse;
    r[lane + 32] = v1 - lse;
}

// ---------------------------------------------------------------------------
// Host side
// ---------------------------------------------------------------------------
extern "C" void kernel_launch(void* const* d_in, const int* in_sizes, int n_in,
                              void* d_out, int out_size)
{
    const float* x    = (const float*)d_in[0];
    const float* wav  = (const float*)d_in[1];
    const float* winv = (const float*)d_in[2];
    const float* w1   = (const float*)d_in[3];
    const float* f1   = (const float*)d_in[4];
    const float* w2   = (const float*)d_in[5];
    const float* f2   = (const float*)d_in[6];
    float* out = (float*)d_out;

    __nv_bfloat16 *W1thi, *W1tlo, *T1thi, *T1tlo, *U1thi, *U1tlo, *Hhi, *Hlo;
    __nv_bfloat16 *W2thi, *W2tlo, *T2thi, *T2tlo, *U2thi, *U2tlo;
    cudaGetSymbolAddress((void**)&W1thi, g_W1thi); cudaGetSymbolAddress((void**)&W1tlo, g_W1tlo);
    cudaGetSymbolAddress((void**)&T1thi, g_T1thi); cudaGetSymbolAddress((void**)&T1tlo, g_T1tlo);
    cudaGetSymbolAddress((void**)&U1thi, g_U1thi); cudaGetSymbolAddress((void**)&U1tlo, g_U1tlo);
    cudaGetSymbolAddress((void**)&Hhi, g_Hhi);     cudaGetSymbolAddress((void**)&Hlo, g_Hlo);
    cudaGetSymbolAddress((void**)&W2thi, g_W2thi); cudaGetSymbolAddress((void**)&W2tlo, g_W2tlo);
    cudaGetSymbolAddress((void**)&T2thi, g_T2thi); cudaGetSymbolAddress((void**)&T2tlo, g_T2tlo);
    cudaGetSymbolAddress((void**)&U2thi, g_U2thi); cudaGetSymbolAddress((void**)&U2tlo, g_U2tlo);

    // --- Small-weight splits (tiny) ---
    split_t_kernel<<<(FIN * HID + 255) / 256, 256>>>(w1, W1thi, W1tlo, FIN, HID);
    split_t_kernel<<<(HID * OUTD + 255) / 256, 256>>>(w2, W2thi, W2tlo, HID, OUTD);

    // --- SMEM sizes: STAGE = BM*256 + BN*256 ---
    constexpr int SMEM_BIG   = 3 * (128 * 256 + 128 * 256);  // 196608
    constexpr int SMEM_SMALL = 3 * (64 * 256 + 64 * 256);    // 98304

    cudaFuncSetAttribute((const void*)gemm_mma_kernel<128,128,32,64,256,1,0,false,false>,
                         cudaFuncAttributeMaxDynamicSharedMemorySize, SMEM_BIG);
    cudaFuncSetAttribute((const void*)gemm_mma_kernel<128,128,32,64,256,1,0,false,true>,
                         cudaFuncAttributeMaxDynamicSharedMemorySize, SMEM_BIG);
    cudaFuncSetAttribute((const void*)gemm_mma_kernel<128,128,32,64,256,1,1,true,false>,
                         cudaFuncAttributeMaxDynamicSharedMemorySize, SMEM_BIG);
    cudaFuncSetAttribute((const void*)gemm_mma_kernel<64,64,16,64,128,0,0,false,false>,
                         cudaFuncAttributeMaxDynamicSharedMemorySize, SMEM_SMALL);
    cudaFuncSetAttribute((const void*)gemm_mma_kernel<64,64,16,64,128,1,0,false,true>,
                         cudaFuncAttributeMaxDynamicSharedMemorySize, SMEM_SMALL);
    cudaFuncSetAttribute((const void*)gemm_mma_kernel<64,64,16,64,128,1,2,false,false>,
                         cudaFuncAttributeMaxDynamicSharedMemorySize, SMEM_SMALL);

    // --- GEMM chain (A fp32 read directly; no big split kernels) ---
    // T1^T = (x @ w1)^T                      A=x fp32 [8192,512], B=w1^T
    gemm_mma_kernel<128,128,32,64,256,1,0,false,false>
        <<<dim3(HID/128, NN/128), 256, SMEM_BIG>>>(
            x, nullptr, W1thi, W1tlo, FIN, nullptr, T1thi, T1tlo, nullptr);
    // (f1*U1)^T = (f1 * (winv @ T1))^T       A=winv fp32, B=T1^T
    gemm_mma_kernel<128,128,32,64,256,1,0,false,true>
        <<<dim3(HID/128, NN/128), 256, SMEM_BIG>>>(
            winv, nullptr, T1thi, T1tlo, NN, nullptr, U1thi, U1tlo, f1);
    // H = relu(wav @ (f1*U1))   row-major [8192,256]
    gemm_mma_kernel<128,128,32,64,256,1,1,true,false>
        <<<dim3(HID/128, NN/128), 256, SMEM_BIG>>>(
            wav, nullptr, U1thi, U1tlo, NN, nullptr, Hhi, Hlo, nullptr);
    // T2^T = (H @ w2)^T                      A=H bf16 pair [8192,256], B=w2^T
    gemm_mma_kernel<64,64,16,64,128,0,0,false,false>
        <<<dim3(OUTD/64, NN/64), 128, SMEM_SMALL>>>(
            Hhi, Hlo, W2thi, W2tlo, HID, nullptr, T2thi, T2tlo, nullptr);
    // (f2*U2)^T = (f2 * (winv @ T2))^T       A=winv fp32, B=T2^T
    gemm_mma_kernel<64,64,16,64,128,1,0,false,true>
        <<<dim3(OUTD/64, NN/64), 128, SMEM_SMALL>>>(
            winv, nullptr, T2thi, T2tlo, NN, nullptr, U2thi, U2tlo, f2);
    // out = wav @ (f2*U2)   fp32 [8192,64]
    gemm_mma_kernel<64,64,16,64,128,1,2,false,false>
        <<<dim3(OUTD/64, NN/64), 128, SMEM_SMALL>>>(
            wav, nullptr, U2thi, U2tlo, NN, out, nullptr, nullptr, nullptr);

    // log_softmax in place
    log_softmax64_kernel<<<NN / 8, dim3(32, 8)>>>(out);
}